// round 8
// baseline (speedup 1.0000x reference)
#include <cuda_runtime.h>

#define Lq 128
#define Bq 128
#define Dq 1024
#define Aq 1024
#define Hq 2048
#define KSPLIT 16
#define KC (Dq / KSPLIT)   // 64 k per split block

typedef unsigned long long ull;

// Scratch (device globals: allocation-free, graph-safe; zero-initialized)
__device__ float g_projp[KSPLIT * Bq * Aq];  // split-K partials (8MB, L2-resident)
__device__ float g_proj[Bq * Aq];            // reduced proj + bias
__device__ float g_eT[Bq * Lq];              // UNNORMALIZED e~ = exp(score+b)*mask, (B,L)
__device__ unsigned g_cnt_col[16];           // proj: blocks done per a-column
__device__ unsigned g_cnt_b[Bq];             // scores blocks done per b
__device__ unsigned g_cnt2_b[Bq];            // attend blocks done per b (for reset)

__device__ __forceinline__ float tanh_fast(float x) {
    float y;
    asm("tanh.approx.f32 %0, %1;" : "=f"(y) : "f"(x));
    return y;
}
__device__ __forceinline__ ull pack2(float x, float y) {
    ull r;
    asm("mov.b64 %0, {%1, %2};" : "=l"(r) : "f"(x), "f"(y));
    return r;
}
__device__ __forceinline__ void unpack2(ull v, float& lo, float& hi) {
    asm("mov.b64 {%0, %1}, %2;" : "=f"(lo), "=f"(hi) : "l"(v));
}
__device__ __forceinline__ ull ffma2(ull a, ull b, ull c) {
    ull d;
    asm("fma.rn.f32x2 %0, %1, %2, %3;" : "=l"(d) : "l"(a), "l"(b), "l"(c));
    return d;
}

// ---------------------------------------------------------------------------
// K1: proj partials + fused tail-reduce.
// Register-tiled f32x2 SGEMM: 128(b) x 64(a), KT=16, split-K=16.
// Grid (16 a-cols, 16 z) = 256 blocks. The LAST block to finish a column
// reduces its 16 partials (+bias) into g_proj and resets the counter
// (threadFenceReduction pattern; graph-replay safe).
// ---------------------------------------------------------------------------
__global__ void __launch_bounds__(256) k_proj(const float* __restrict__ S,
                                              const float* __restrict__ W,
                                              const float* __restrict__ bsa) {
    const int a0    = blockIdx.x * 64;
    const int kbase = blockIdx.y * KC;

    __shared__ float As[16][132];  // [k][m]
    __shared__ float Bs[16][68];   // [k][n]
    __shared__ unsigned s_rank;

    const int t  = threadIdx.x;
    const int ar = t >> 1;
    const int ac = (t & 1) * 8;
    const int br = t >> 2;
    const int bc = (t & 3) * 4;
    const int tx = t & 15;
    const int ty = t >> 4;

    ull acc[4][4];
#pragma unroll
    for (int i = 0; i < 4; ++i)
#pragma unroll
        for (int j = 0; j < 4; ++j) acc[i][j] = 0ull;

    for (int kt = 0; kt < KC; kt += 16) {
        const int k0 = kbase + kt;
        float4 av0 = *(const float4*)(S + (size_t)ar * Dq + k0 + ac);
        float4 av1 = *(const float4*)(S + (size_t)ar * Dq + k0 + ac + 4);
        float4 bv  = *(const float4*)(W + (size_t)(a0 + br) * Dq + k0 + bc);
        __syncthreads();
        As[ac + 0][ar] = av0.x;  As[ac + 1][ar] = av0.y;
        As[ac + 2][ar] = av0.z;  As[ac + 3][ar] = av0.w;
        As[ac + 4][ar] = av1.x;  As[ac + 5][ar] = av1.y;
        As[ac + 6][ar] = av1.z;  As[ac + 7][ar] = av1.w;
        Bs[bc + 0][br] = bv.x;   Bs[bc + 1][br] = bv.y;
        Bs[bc + 2][br] = bv.z;   Bs[bc + 3][br] = bv.w;
        __syncthreads();
#pragma unroll
        for (int kk = 0; kk < 16; ++kk) {
            ulonglong2 a01 = *(const ulonglong2*)&As[kk][ty * 8];
            ulonglong2 a23 = *(const ulonglong2*)&As[kk][ty * 8 + 4];
            float4 b = *(const float4*)&Bs[kk][tx * 4];
            ull b0 = pack2(b.x, b.x), b1 = pack2(b.y, b.y);
            ull b2 = pack2(b.z, b.z), b3 = pack2(b.w, b.w);
            acc[0][0] = ffma2(a01.x, b0, acc[0][0]);
            acc[0][1] = ffma2(a01.x, b1, acc[0][1]);
            acc[0][2] = ffma2(a01.x, b2, acc[0][2]);
            acc[0][3] = ffma2(a01.x, b3, acc[0][3]);
            acc[1][0] = ffma2(a01.y, b0, acc[1][0]);
            acc[1][1] = ffma2(a01.y, b1, acc[1][1]);
            acc[1][2] = ffma2(a01.y, b2, acc[1][2]);
            acc[1][3] = ffma2(a01.y, b3, acc[1][3]);
            acc[2][0] = ffma2(a23.x, b0, acc[2][0]);
            acc[2][1] = ffma2(a23.x, b1, acc[2][1]);
            acc[2][2] = ffma2(a23.x, b2, acc[2][2]);
            acc[2][3] = ffma2(a23.x, b3, acc[2][3]);
            acc[3][0] = ffma2(a23.y, b0, acc[3][0]);
            acc[3][1] = ffma2(a23.y, b1, acc[3][1]);
            acc[3][2] = ffma2(a23.y, b2, acc[3][2]);
            acc[3][3] = ffma2(a23.y, b3, acc[3][3]);
        }
    }

    float* base = g_projp + (size_t)blockIdx.y * Bq * Aq + a0 + tx * 4;
#pragma unroll
    for (int mi = 0; mi < 4; ++mi) {
        float4 r0, r1;
        unpack2(acc[mi][0], r0.x, r1.x);
        unpack2(acc[mi][1], r0.y, r1.y);
        unpack2(acc[mi][2], r0.z, r1.z);
        unpack2(acc[mi][3], r0.w, r1.w);
        const int m = ty * 8 + 2 * mi;
        *(float4*)(base + (size_t)m * Aq)       = r0;
        *(float4*)(base + (size_t)(m + 1) * Aq) = r1;
    }

    // --- fused reduce: last block of this a-column sums the 16 partials ---
    __syncthreads();
    if (t == 0) {
        __threadfence();
        s_rank = atomicAdd(&g_cnt_col[blockIdx.x], 1u);
    }
    __syncthreads();
    if (s_rank == KSPLIT - 1) {
        __threadfence();  // acquire: other blocks' partials now visible
#pragma unroll
        for (int j = 0; j < 8; ++j) {
            const int f  = t + j * 256;        // float4 idx in 128x64 tile
            const int b  = f >> 4;
            const int a4 = (f & 15) << 2;
            const size_t off = (size_t)b * Aq + a0 + a4;
            float4 s = *(const float4*)(bsa + a0 + a4);
            for (int z = 0; z < KSPLIT; ++z) {
                float4 p = *(const float4*)(g_projp + (size_t)z * Bq * Aq + off);
                s.x += p.x;  s.y += p.y;  s.z += p.z;  s.w += p.w;
            }
            *(float4*)(g_proj + off) = s;
        }
        __syncthreads();
        if (t == 0) g_cnt_col[blockIdx.x] = 0;   // reset for next launch
    }
}

// ---------------------------------------------------------------------------
// K2: fused scores + attend (per-b producer/consumer pipeline in one launch).
// Blocks 0..2047  : scores role — e~[b,l], then release g_cnt_b[b].
// Blocks 2048..3071: attend role — spin until g_cnt_b[b]==16, then stream.
// Dispatch is in bid order, so scores blocks are always scheduled before
// attend blocks; spinning attend blocks can't starve unscheduled scores.
// Counters self-reset via g_cnt2_b (last attend block per b).
// ---------------------------------------------------------------------------
__global__ void __launch_bounds__(256) k_sa(const float* __restrict__ uh,
                                            const float* __restrict__ w1,
                                            const float* __restrict__ mask,
                                            const float* __restrict__ ba1,
                                            const float* __restrict__ xs,
                                            float* __restrict__ e_out,
                                            float* __restrict__ out) {
    const int bid = blockIdx.x;
    const int t   = threadIdx.x;

    __shared__ float ps[Aq];
    __shared__ float ws[Aq];
    __shared__ float  es[Lq];
    __shared__ float  red[4];
    __shared__ float4 pacc[256];

    if (bid < 2048) {
        // ------------------------- scores role -------------------------
        const int b  = bid >> 4;
        const int l0 = (bid & 15) << 3;
        const int i4 = t * 4;

        *(float4*)&ps[i4] = *(const float4*)(g_proj + (size_t)b * Aq + i4);
        *(float4*)&ws[i4] = *(const float4*)(w1 + i4);
        __syncthreads();

        const int w    = t >> 5;
        const int lane = t & 31;
        const int l    = l0 + w;
        const float* u = uh + (size_t)(l * Bq + b) * Aq;

        float acc = 0.f;
#pragma unroll
        for (int i = 0; i < 8; ++i) {
            int idx = i * 128 + lane * 4;
            float4 u4 = __ldcs((const float4*)(u + idx));
            float4 p4 = *(const float4*)&ps[idx];
            float4 w4 = *(const float4*)&ws[idx];
            acc = fmaf(w4.x, tanh_fast(p4.x + u4.x), acc);
            acc = fmaf(w4.y, tanh_fast(p4.y + u4.y), acc);
            acc = fmaf(w4.z, tanh_fast(p4.z + u4.z), acc);
            acc = fmaf(w4.w, tanh_fast(p4.w + u4.w), acc);
        }
#pragma unroll
        for (int off = 16; off; off >>= 1)
            acc += __shfl_xor_sync(0xffffffffu, acc, off);
        if (lane == 0)
            g_eT[b * Lq + l] = __expf(acc + ba1[0]) * mask[l * Bq + b];

        __syncthreads();
        if (t == 0) {
            __threadfence();                  // release e~ writes
            atomicAdd(&g_cnt_b[b], 1u);
        }
    } else {
        // ------------------------- attend role -------------------------
        const int ab = bid - 2048;
        const int b  = ab >> 3;
        const int h0 = (ab & 7) * 256;

        if (t == 0) {
            while (*((volatile unsigned*)&g_cnt_b[b]) < 16u)
                __nanosleep(64);
            __threadfence();                  // acquire e~ writes
        }
        __syncthreads();

        float ev = 0.f;
        if (t < 128) ev = g_eT[b * Lq + t];
        float v = ev;
#pragma unroll
        for (int off = 16; off; off >>= 1)
            v += __shfl_xor_sync(0xffffffffu, v, off);
        if (t < 128) {
            if ((t & 31) == 0) red[t >> 5] = v;
            es[t] = ev;
        }
        __syncthreads();
        const float inv = 1.f / ((red[0] + red[1]) + (red[2] + red[3]));
        if (h0 == 0 && t < 128) e_out[t * Bq + b] = es[t] * inv;

        // all threads past g_eT/g_cnt_b reads -> last attend block resets
        if (t == 0) {
            unsigned r = atomicAdd(&g_cnt2_b[b], 1u);
            if (r == 7u) { g_cnt_b[b] = 0u; g_cnt2_b[b] = 0u; }
        }

        const int col = t & 63;
        const int g   = t >> 6;
        const float* base = xs + (size_t)(g * 32) * Bq * Hq +
                            (size_t)b * Hq + h0 + col * 4;
        float4 a0 = make_float4(0.f, 0.f, 0.f, 0.f);
        float4 a1 = make_float4(0.f, 0.f, 0.f, 0.f);
#pragma unroll
        for (int i = 0; i < 32; i += 2) {
            float4 v0 = __ldcs((const float4*)(base + (size_t)(i + 0) * Bq * Hq));
            float4 v1 = __ldcs((const float4*)(base + (size_t)(i + 1) * Bq * Hq));
            float e0 = es[g * 32 + i + 0];
            float e1 = es[g * 32 + i + 1];
            a0.x = fmaf(e0, v0.x, a0.x);  a0.y = fmaf(e0, v0.y, a0.y);
            a0.z = fmaf(e0, v0.z, a0.z);  a0.w = fmaf(e0, v0.w, a0.w);
            a1.x = fmaf(e1, v1.x, a1.x);  a1.y = fmaf(e1, v1.y, a1.y);
            a1.z = fmaf(e1, v1.z, a1.z);  a1.w = fmaf(e1, v1.w, a1.w);
        }
        a0.x += a1.x;  a0.y += a1.y;  a0.z += a1.z;  a0.w += a1.w;
        pacc[t] = a0;
        __syncthreads();
        if (g == 0) {
            float4 p1 = pacc[col + 64];
            float4 p2 = pacc[col + 128];
            float4 p3 = pacc[col + 192];
            a0.x = ((a0.x + p1.x) + (p2.x + p3.x)) * inv;
            a0.y = ((a0.y + p1.y) + (p2.y + p3.y)) * inv;
            a0.z = ((a0.z + p1.z) + (p2.z + p3.z)) * inv;
            a0.w = ((a0.w + p1.w) + (p2.w + p3.w)) * inv;
            *(float4*)(out + (size_t)b * Hq + h0 + col * 4) = a0;
        }
    }
}

// ---------------------------------------------------------------------------
extern "C" void kernel_launch(void* const* d_in, const int* in_sizes, int n_in,
                              void* d_out, int out_size) {
    const float* s_tm1 = (const float*)d_in[0];
    const float* xs_h  = (const float*)d_in[1];
    const float* uh    = (const float*)d_in[2];
    const float* mask  = (const float*)d_in[3];
    const float* W_sa  = (const float*)d_in[4];
    const float* b_sa  = (const float*)d_in[5];
    const float* w_a1  = (const float*)d_in[6];
    const float* b_a1  = (const float*)d_in[7];
    float* out = (float*)d_out;  // [0 : L*B) = e_ij, [L*B : ) = attend

    k_proj<<<dim3(16, KSPLIT), 256>>>(s_tm1, W_sa, b_sa);
    k_sa<<<3072, 256>>>(uh, w_a1, mask, b_a1, xs_h, out, out + Lq * Bq);
}

// round 10
// speedup vs baseline: 1.1191x; 1.1191x over previous
#include <cuda_runtime.h>

#define Lq 128
#define Bq 128
#define Dq 1024
#define Aq 1024
#define Hq 2048
#define KSPLIT 16
#define KC (Dq / KSPLIT)   // 64 k per split block

typedef unsigned long long ull;

// Scratch (device globals: allocation-free, graph-safe; zero-initialized)
__device__ float g_projp[KSPLIT * Bq * Aq];  // split-K partials (8MB, L2-resident)
__device__ float g_proj[Bq * Aq];            // reduced proj + bias
__device__ float g_eT[Bq * Lq];              // UNNORMALIZED e~ = exp(score+b)*mask, (B,L)
__device__ unsigned g_cnt_b[Bq];             // scores blocks done per b
__device__ unsigned g_cnt2_b[Bq];            // attend blocks done per b (for reset)

__device__ __forceinline__ float tanh_fast(float x) {
    float y;
    asm("tanh.approx.f32 %0, %1;" : "=f"(y) : "f"(x));
    return y;
}
__device__ __forceinline__ ull pack2(float x, float y) {
    ull r;
    asm("mov.b64 %0, {%1, %2};" : "=l"(r) : "f"(x), "f"(y));
    return r;
}
__device__ __forceinline__ void unpack2(ull v, float& lo, float& hi) {
    asm("mov.b64 {%0, %1}, %2;" : "=f"(lo), "=f"(hi) : "l"(v));
}
__device__ __forceinline__ ull ffma2(ull a, ull b, ull c) {
    ull d;
    asm("fma.rn.f32x2 %0, %1, %2, %3;" : "=l"(d) : "l"(a), "l"(b), "l"(c));
    return d;
}

// ---------------------------------------------------------------------------
// K1: proj partials. Register-tiled f32x2 SGEMM: 128(b) x 64(a), KT=16,
// split-K=16. Grid (16, 16) = 256 blocks, 256 threads.
// ---------------------------------------------------------------------------
__global__ void __launch_bounds__(256) k_proj(const float* __restrict__ S,
                                              const float* __restrict__ W) {
    const int a0    = blockIdx.x * 64;
    const int kbase = blockIdx.y * KC;

    __shared__ float As[16][132];  // [k][m]
    __shared__ float Bs[16][68];   // [k][n]

    const int t  = threadIdx.x;
    const int ar = t >> 1;
    const int ac = (t & 1) * 8;
    const int br = t >> 2;
    const int bc = (t & 3) * 4;
    const int tx = t & 15;
    const int ty = t >> 4;

    ull acc[4][4];
#pragma unroll
    for (int i = 0; i < 4; ++i)
#pragma unroll
        for (int j = 0; j < 4; ++j) acc[i][j] = 0ull;

    for (int kt = 0; kt < KC; kt += 16) {
        const int k0 = kbase + kt;
        float4 av0 = *(const float4*)(S + (size_t)ar * Dq + k0 + ac);
        float4 av1 = *(const float4*)(S + (size_t)ar * Dq + k0 + ac + 4);
        float4 bv  = *(const float4*)(W + (size_t)(a0 + br) * Dq + k0 + bc);
        __syncthreads();
        As[ac + 0][ar] = av0.x;  As[ac + 1][ar] = av0.y;
        As[ac + 2][ar] = av0.z;  As[ac + 3][ar] = av0.w;
        As[ac + 4][ar] = av1.x;  As[ac + 5][ar] = av1.y;
        As[ac + 6][ar] = av1.z;  As[ac + 7][ar] = av1.w;
        Bs[bc + 0][br] = bv.x;   Bs[bc + 1][br] = bv.y;
        Bs[bc + 2][br] = bv.z;   Bs[bc + 3][br] = bv.w;
        __syncthreads();
#pragma unroll
        for (int kk = 0; kk < 16; ++kk) {
            ulonglong2 a01 = *(const ulonglong2*)&As[kk][ty * 8];
            ulonglong2 a23 = *(const ulonglong2*)&As[kk][ty * 8 + 4];
            float4 b = *(const float4*)&Bs[kk][tx * 4];
            ull b0 = pack2(b.x, b.x), b1 = pack2(b.y, b.y);
            ull b2 = pack2(b.z, b.z), b3 = pack2(b.w, b.w);
            acc[0][0] = ffma2(a01.x, b0, acc[0][0]);
            acc[0][1] = ffma2(a01.x, b1, acc[0][1]);
            acc[0][2] = ffma2(a01.x, b2, acc[0][2]);
            acc[0][3] = ffma2(a01.x, b3, acc[0][3]);
            acc[1][0] = ffma2(a01.y, b0, acc[1][0]);
            acc[1][1] = ffma2(a01.y, b1, acc[1][1]);
            acc[1][2] = ffma2(a01.y, b2, acc[1][2]);
            acc[1][3] = ffma2(a01.y, b3, acc[1][3]);
            acc[2][0] = ffma2(a23.x, b0, acc[2][0]);
            acc[2][1] = ffma2(a23.x, b1, acc[2][1]);
            acc[2][2] = ffma2(a23.x, b2, acc[2][2]);
            acc[2][3] = ffma2(a23.x, b3, acc[2][3]);
            acc[3][0] = ffma2(a23.y, b0, acc[3][0]);
            acc[3][1] = ffma2(a23.y, b1, acc[3][1]);
            acc[3][2] = ffma2(a23.y, b2, acc[3][2]);
            acc[3][3] = ffma2(a23.y, b3, acc[3][3]);
        }
    }

    float* base = g_projp + (size_t)blockIdx.y * Bq * Aq + a0 + tx * 4;
#pragma unroll
    for (int mi = 0; mi < 4; ++mi) {
        float4 r0, r1;
        unpack2(acc[mi][0], r0.x, r1.x);
        unpack2(acc[mi][1], r0.y, r1.y);
        unpack2(acc[mi][2], r0.z, r1.z);
        unpack2(acc[mi][3], r0.w, r1.w);
        const int m = ty * 8 + 2 * mi;
        *(float4*)(base + (size_t)m * Aq)       = r0;
        *(float4*)(base + (size_t)(m + 1) * Aq) = r1;
    }
}

// ---------------------------------------------------------------------------
// K2: g_proj = sum_z partials + bias.
// EXACTLY covers Bq*Aq = 131072 floats = 32768 float4 = 128 blocks x 256 thr.
// (Round-9 crash: grid 1024 overran g_proj by 8x.)
// ---------------------------------------------------------------------------
__global__ void __launch_bounds__(256) k_reduce(const float* __restrict__ bsa) {
    const int idx = (blockIdx.x * 256 + threadIdx.x) * 4;
    const int a   = idx & (Aq - 1);
    float4 s = *(const float4*)(bsa + a);
#pragma unroll
    for (int z = 0; z < KSPLIT; ++z) {
        float4 p = *(const float4*)(g_projp + (size_t)z * Bq * Aq + idx);
        s.x += p.x;  s.y += p.y;  s.z += p.z;  s.w += p.w;
    }
    *(float4*)(g_proj + idx) = s;
}

// ---------------------------------------------------------------------------
// K3: fused scores + attend, B-MAJOR ROLE INTERLEAVING.
// bid -> b = bid/24, r = bid%24. r<16: scores role (l0 = r*8).
//                               r>=16: attend role (h0 = (r-16)*256).
// Every dispatch wave contains both roles in steady proportion, so attend
// (xs_h stream) for early b's overlaps scores (uh stream) for later b's.
// Deadlock-free: scores bids for b precede attend bids for b.
// Grid: B*24 = 3072 blocks, 256 threads.
// ---------------------------------------------------------------------------
__global__ void __launch_bounds__(256) k_sa(const float* __restrict__ uh,
                                            const float* __restrict__ w1,
                                            const float* __restrict__ mask,
                                            const float* __restrict__ ba1,
                                            const float* __restrict__ xs,
                                            float* __restrict__ e_out,
                                            float* __restrict__ out) {
    const int bid = blockIdx.x;
    const int b   = bid / 24;
    const int r   = bid % 24;
    const int t   = threadIdx.x;

    __shared__ float ps[Aq];
    __shared__ float ws[Aq];
    __shared__ float  es[Lq];
    __shared__ float  red[4];
    __shared__ float4 pacc[256];

    if (r < 16) {
        // ------------------------- scores role -------------------------
        const int l0 = r << 3;
        const int i4 = t * 4;

        *(float4*)&ps[i4] = *(const float4*)(g_proj + (size_t)b * Aq + i4);
        *(float4*)&ws[i4] = *(const float4*)(w1 + i4);
        __syncthreads();

        const int w    = t >> 5;
        const int lane = t & 31;
        const int l    = l0 + w;
        const float* u = uh + (size_t)(l * Bq + b) * Aq;

        float acc = 0.f;
#pragma unroll
        for (int i = 0; i < 8; ++i) {
            int idx = i * 128 + lane * 4;
            float4 u4 = __ldcs((const float4*)(u + idx));
            float4 p4 = *(const float4*)&ps[idx];
            float4 w4 = *(const float4*)&ws[idx];
            acc = fmaf(w4.x, tanh_fast(p4.x + u4.x), acc);
            acc = fmaf(w4.y, tanh_fast(p4.y + u4.y), acc);
            acc = fmaf(w4.z, tanh_fast(p4.z + u4.z), acc);
            acc = fmaf(w4.w, tanh_fast(p4.w + u4.w), acc);
        }
#pragma unroll
        for (int off = 16; off; off >>= 1)
            acc += __shfl_xor_sync(0xffffffffu, acc, off);
        if (lane == 0)
            g_eT[b * Lq + l] = __expf(acc + ba1[0]) * mask[l * Bq + b];

        __syncthreads();
        if (t == 0) {
            __threadfence();                  // release e~ writes
            atomicAdd(&g_cnt_b[b], 1u);
        }
    } else {
        // ------------------------- attend role -------------------------
        const int h0 = (r - 16) * 256;

        if (t == 0) {
            while (*((volatile unsigned*)&g_cnt_b[b]) < 16u)
                __nanosleep(64);
            __threadfence();                  // acquire e~ writes
        }
        __syncthreads();

        float ev = 0.f;
        if (t < 128) ev = g_eT[b * Lq + t];
        float v = ev;
#pragma unroll
        for (int off = 16; off; off >>= 1)
            v += __shfl_xor_sync(0xffffffffu, v, off);
        if (t < 128) {
            if ((t & 31) == 0) red[t >> 5] = v;
            es[t] = ev;
        }
        __syncthreads();
        const float inv = 1.f / ((red[0] + red[1]) + (red[2] + red[3]));
        if (h0 == 0 && t < 128) e_out[t * Bq + b] = es[t] * inv;

        // all threads past g_eT/g_cnt_b reads -> last attend block resets
        if (t == 0) {
            unsigned rr = atomicAdd(&g_cnt2_b[b], 1u);
            if (rr == 7u) { g_cnt_b[b] = 0u; g_cnt2_b[b] = 0u; }
        }

        const int col = t & 63;
        const int g   = t >> 6;
        const float* base = xs + (size_t)(g * 32) * Bq * Hq +
                            (size_t)b * Hq + h0 + col * 4;
        float4 a0 = make_float4(0.f, 0.f, 0.f, 0.f);
        float4 a1 = make_float4(0.f, 0.f, 0.f, 0.f);
#pragma unroll
        for (int i = 0; i < 32; i += 2) {
            float4 v0 = __ldcs((const float4*)(base + (size_t)(i + 0) * Bq * Hq));
            float4 v1 = __ldcs((const float4*)(base + (size_t)(i + 1) * Bq * Hq));
            float e0 = es[g * 32 + i + 0];
            float e1 = es[g * 32 + i + 1];
            a0.x = fmaf(e0, v0.x, a0.x);  a0.y = fmaf(e0, v0.y, a0.y);
            a0.z = fmaf(e0, v0.z, a0.z);  a0.w = fmaf(e0, v0.w, a0.w);
            a1.x = fmaf(e1, v1.x, a1.x);  a1.y = fmaf(e1, v1.y, a1.y);
            a1.z = fmaf(e1, v1.z, a1.z);  a1.w = fmaf(e1, v1.w, a1.w);
        }
        a0.x += a1.x;  a0.y += a1.y;  a0.z += a1.z;  a0.w += a1.w;
        pacc[t] = a0;
        __syncthreads();
        if (g == 0) {
            float4 p1 = pacc[col + 64];
            float4 p2 = pacc[col + 128];
            float4 p3 = pacc[col + 192];
            a0.x = ((a0.x + p1.x) + (p2.x + p3.x)) * inv;
            a0.y = ((a0.y + p1.y) + (p2.y + p3.y)) * inv;
            a0.z = ((a0.z + p1.z) + (p2.z + p3.z)) * inv;
            a0.w = ((a0.w + p1.w) + (p2.w + p3.w)) * inv;
            *(float4*)(out + (size_t)b * Hq + h0 + col * 4) = a0;
        }
    }
}

// ---------------------------------------------------------------------------
extern "C" void kernel_launch(void* const* d_in, const int* in_sizes, int n_in,
                              void* d_out, int out_size) {
    const float* s_tm1 = (const float*)d_in[0];
    const float* xs_h  = (const float*)d_in[1];
    const float* uh    = (const float*)d_in[2];
    const float* mask  = (const float*)d_in[3];
    const float* W_sa  = (const float*)d_in[4];
    const float* b_sa  = (const float*)d_in[5];
    const float* w_a1  = (const float*)d_in[6];
    const float* b_a1  = (const float*)d_in[7];
    float* out = (float*)d_out;  // [0 : L*B) = e_ij, [L*B : ) = attend

    k_proj<<<dim3(16, KSPLIT), 256>>>(s_tm1, W_sa);
    k_reduce<<<128, 256>>>(b_sa);
    k_sa<<<3072, 256>>>(uh, w_a1, mask, b_a1, xs_h, out, out + Lq * Bq);
}

// round 12
// speedup vs baseline: 1.1211x; 1.0018x over previous
#include <cuda_runtime.h>

#define Lq 128
#define Bq 128
#define Dq 1024
#define Aq 1024
#define Hq 2048
#define KSPLIT 32
#define KC (Dq / KSPLIT)   // 32 k per split block

typedef unsigned long long ull;

// Scratch (device globals: allocation-free, graph-safe)
__device__ float g_projp[KSPLIT * Bq * Aq];  // split-K partials (16MB, L2-resident)
__device__ float g_proj[Bq * Aq];            // reduced proj + bias
__device__ float g_eT[Bq * Lq];              // UNNORMALIZED e~ = exp(score+b)*mask, (B,L)

__device__ __forceinline__ float tanh_fast(float x) {
    float y;
    asm("tanh.approx.f32 %0, %1;" : "=f"(y) : "f"(x));
    return y;
}
__device__ __forceinline__ ull pack2(float x, float y) {
    ull r;
    asm("mov.b64 %0, {%1, %2};" : "=l"(r) : "f"(x), "f"(y));
    return r;
}
__device__ __forceinline__ void unpack2(ull v, float& lo, float& hi) {
    asm("mov.b64 {%0, %1}, %2;" : "=f"(lo), "=f"(hi) : "l"(v));
}
__device__ __forceinline__ ull ffma2(ull a, ull b, ull c) {
    ull d;
    asm("fma.rn.f32x2 %0, %1, %2, %3;" : "=l"(d) : "l"(a), "l"(b), "l"(c));
    return d;
}

// ---------------------------------------------------------------------------
// K1: proj partials. Register-tiled f32x2 SGEMM: 128(b) x 64(a), KT=16,
// split-K=32. Grid (16, 32) = 512 blocks (~3.5/SM, occ ~40-45%) so warps
// from co-resident blocks cover LDS latency and sync bubbles.
// 256 threads; 8(m) x 4(n) register tile per thread as f32x2 pairs.
// ---------------------------------------------------------------------------
__global__ void __launch_bounds__(256) k_proj(const float* __restrict__ S,
                                              const float* __restrict__ W) {
    const int a0    = blockIdx.x * 64;
    const int kbase = blockIdx.y * KC;

    __shared__ float As[16][132];  // [k][m]
    __shared__ float Bs[16][68];   // [k][n]

    const int t  = threadIdx.x;
    const int ar = t >> 1;
    const int ac = (t & 1) * 8;
    const int br = t >> 2;
    const int bc = (t & 3) * 4;
    const int tx = t & 15;
    const int ty = t >> 4;

    ull acc[4][4];
#pragma unroll
    for (int i = 0; i < 4; ++i)
#pragma unroll
        for (int j = 0; j < 4; ++j) acc[i][j] = 0ull;

#pragma unroll
    for (int kt = 0; kt < KC; kt += 16) {
        const int k0 = kbase + kt;
        float4 av0 = *(const float4*)(S + (size_t)ar * Dq + k0 + ac);
        float4 av1 = *(const float4*)(S + (size_t)ar * Dq + k0 + ac + 4);
        float4 bv  = *(const float4*)(W + (size_t)(a0 + br) * Dq + k0 + bc);
        __syncthreads();
        As[ac + 0][ar] = av0.x;  As[ac + 1][ar] = av0.y;
        As[ac + 2][ar] = av0.z;  As[ac + 3][ar] = av0.w;
        As[ac + 4][ar] = av1.x;  As[ac + 5][ar] = av1.y;
        As[ac + 6][ar] = av1.z;  As[ac + 7][ar] = av1.w;
        Bs[bc + 0][br] = bv.x;   Bs[bc + 1][br] = bv.y;
        Bs[bc + 2][br] = bv.z;   Bs[bc + 3][br] = bv.w;
        __syncthreads();
#pragma unroll
        for (int kk = 0; kk < 16; ++kk) {
            ulonglong2 a01 = *(const ulonglong2*)&As[kk][ty * 8];
            ulonglong2 a23 = *(const ulonglong2*)&As[kk][ty * 8 + 4];
            float4 b = *(const float4*)&Bs[kk][tx * 4];
            ull b0 = pack2(b.x, b.x), b1 = pack2(b.y, b.y);
            ull b2 = pack2(b.z, b.z), b3 = pack2(b.w, b.w);
            acc[0][0] = ffma2(a01.x, b0, acc[0][0]);
            acc[0][1] = ffma2(a01.x, b1, acc[0][1]);
            acc[0][2] = ffma2(a01.x, b2, acc[0][2]);
            acc[0][3] = ffma2(a01.x, b3, acc[0][3]);
            acc[1][0] = ffma2(a01.y, b0, acc[1][0]);
            acc[1][1] = ffma2(a01.y, b1, acc[1][1]);
            acc[1][2] = ffma2(a01.y, b2, acc[1][2]);
            acc[1][3] = ffma2(a01.y, b3, acc[1][3]);
            acc[2][0] = ffma2(a23.x, b0, acc[2][0]);
            acc[2][1] = ffma2(a23.x, b1, acc[2][1]);
            acc[2][2] = ffma2(a23.x, b2, acc[2][2]);
            acc[2][3] = ffma2(a23.x, b3, acc[2][3]);
            acc[3][0] = ffma2(a23.y, b0, acc[3][0]);
            acc[3][1] = ffma2(a23.y, b1, acc[3][1]);
            acc[3][2] = ffma2(a23.y, b2, acc[3][2]);
            acc[3][3] = ffma2(a23.y, b3, acc[3][3]);
        }
    }

    float* base = g_projp + (size_t)blockIdx.y * Bq * Aq + a0 + tx * 4;
#pragma unroll
    for (int mi = 0; mi < 4; ++mi) {
        float4 r0, r1;
        unpack2(acc[mi][0], r0.x, r1.x);
        unpack2(acc[mi][1], r0.y, r1.y);
        unpack2(acc[mi][2], r0.z, r1.z);
        unpack2(acc[mi][3], r0.w, r1.w);
        const int m = ty * 8 + 2 * mi;
        *(float4*)(base + (size_t)m * Aq)       = r0;
        *(float4*)(base + (size_t)(m + 1) * Aq) = r1;
    }
}

// ---------------------------------------------------------------------------
// K2: g_proj = sum_z partials + bias.
// EXACTLY covers Bq*Aq = 131072 floats = 32768 float4 = 128 blocks x 256 thr.
// Partials are L2-resident (16MB).
// ---------------------------------------------------------------------------
__global__ void __launch_bounds__(256) k_reduce(const float* __restrict__ bsa) {
    const int idx = (blockIdx.x * 256 + threadIdx.x) * 4;
    const int a   = idx & (Aq - 1);
    float4 s = *(const float4*)(bsa + a);
#pragma unroll
    for (int z = 0; z < KSPLIT; ++z) {
        float4 p = *(const float4*)(g_projp + (size_t)z * Bq * Aq + idx);
        s.x += p.x;  s.y += p.y;  s.z += p.z;  s.w += p.w;
    }
    *(float4*)(g_proj + idx) = s;
}

// ---------------------------------------------------------------------------
// K3: e~[b,l] = exp(b_a1 + sum_a w_a1[a]*tanh(proj[b,a]+uh[l,b,a])) * mask
// Warp per (l,b); 8 warps share one b. Softmax numerator fused in epilogue.
// Grid: B * L/8 = 2048 blocks, 256 threads.
// ---------------------------------------------------------------------------
__global__ void __launch_bounds__(256) k_scores(const float* __restrict__ uh,
                                                const float* __restrict__ w1,
                                                const float* __restrict__ mask,
                                                const float* __restrict__ ba1) {
    const int b  = blockIdx.x >> 4;
    const int l0 = (blockIdx.x & 15) << 3;
    __shared__ float ps[Aq];
    __shared__ float ws[Aq];
    const int t  = threadIdx.x;
    const int i4 = t * 4;

    *(float4*)&ps[i4] = *(const float4*)(g_proj + (size_t)b * Aq + i4);
    *(float4*)&ws[i4] = *(const float4*)(w1 + i4);
    __syncthreads();

    const int w    = t >> 5;
    const int lane = t & 31;
    const int l    = l0 + w;
    const float* u = uh + (size_t)(l * Bq + b) * Aq;

    float acc = 0.f;
#pragma unroll
    for (int i = 0; i < 8; ++i) {
        int idx = i * 128 + lane * 4;
        float4 u4 = __ldcs((const float4*)(u + idx));
        float4 p4 = *(const float4*)&ps[idx];
        float4 w4 = *(const float4*)&ws[idx];
        acc = fmaf(w4.x, tanh_fast(p4.x + u4.x), acc);
        acc = fmaf(w4.y, tanh_fast(p4.y + u4.y), acc);
        acc = fmaf(w4.z, tanh_fast(p4.z + u4.z), acc);
        acc = fmaf(w4.w, tanh_fast(p4.w + u4.w), acc);
    }
#pragma unroll
    for (int off = 16; off; off >>= 1)
        acc += __shfl_xor_sync(0xffffffffu, acc, off);
    if (lane == 0)
        g_eT[b * Lq + l] = __expf(acc + ba1[0]) * mask[l * Bq + b];
}

// ---------------------------------------------------------------------------
// K4: attend[b,h] = (1/S_b) * sum_l e~[l,b] * xs_h[l,b,h];  S_b = sum_l e~.
// Block = (b, 256-wide h chunk), 256 threads = 64 cols(x4) * 4 l-groups.
// h0==0 blocks also write normalized e_ij. Grid: B*8 = 1024 blocks.
// ---------------------------------------------------------------------------
__global__ void __launch_bounds__(256) k_attend(const float* __restrict__ xs,
                                                float* __restrict__ e_out,
                                                float* __restrict__ out) {
    const int b  = blockIdx.x >> 3;
    const int h0 = (blockIdx.x & 7) * 256;
    const int t  = threadIdx.x;

    __shared__ float  es[Lq];
    __shared__ float  red[4];
    __shared__ float4 pacc[256];

    float ev = 0.f;
    if (t < 128) ev = g_eT[b * Lq + t];
    float v = ev;
#pragma unroll
    for (int off = 16; off; off >>= 1)
        v += __shfl_xor_sync(0xffffffffu, v, off);
    if (t < 128) {
        if ((t & 31) == 0) red[t >> 5] = v;
        es[t] = ev;
    }
    __syncthreads();
    const float inv = 1.f / ((red[0] + red[1]) + (red[2] + red[3]));
    if (h0 == 0 && t < 128) e_out[t * Bq + b] = es[t] * inv;

    const int col = t & 63;
    const int g   = t >> 6;
    const float* base = xs + (size_t)(g * 32) * Bq * Hq +
                        (size_t)b * Hq + h0 + col * 4;
    float4 a0 = make_float4(0.f, 0.f, 0.f, 0.f);
    float4 a1 = make_float4(0.f, 0.f, 0.f, 0.f);
#pragma unroll
    for (int i = 0; i < 32; i += 2) {
        float4 v0 = __ldcs((const float4*)(base + (size_t)(i + 0) * Bq * Hq));
        float4 v1 = __ldcs((const float4*)(base + (size_t)(i + 1) * Bq * Hq));
        float e0 = es[g * 32 + i + 0];
        float e1 = es[g * 32 + i + 1];
        a0.x = fmaf(e0, v0.x, a0.x);  a0.y = fmaf(e0, v0.y, a0.y);
        a0.z = fmaf(e0, v0.z, a0.z);  a0.w = fmaf(e0, v0.w, a0.w);
        a1.x = fmaf(e1, v1.x, a1.x);  a1.y = fmaf(e1, v1.y, a1.y);
        a1.z = fmaf(e1, v1.z, a1.z);  a1.w = fmaf(e1, v1.w, a1.w);
    }
    a0.x += a1.x;  a0.y += a1.y;  a0.z += a1.z;  a0.w += a1.w;
    pacc[t] = a0;
    __syncthreads();
    if (g == 0) {
        float4 p1 = pacc[col + 64];
        float4 p2 = pacc[col + 128];
        float4 p3 = pacc[col + 192];
        a0.x = ((a0.x + p1.x) + (p2.x + p3.x)) * inv;
        a0.y = ((a0.y + p1.y) + (p2.y + p3.y)) * inv;
        a0.z = ((a0.z + p1.z) + (p2.z + p3.z)) * inv;
        a0.w = ((a0.w + p1.w) + (p2.w + p3.w)) * inv;
        *(float4*)(out + (size_t)b * Hq + h0 + col * 4) = a0;
    }
}

// ---------------------------------------------------------------------------
extern "C" void kernel_launch(void* const* d_in, const int* in_sizes, int n_in,
                              void* d_out, int out_size) {
    const float* s_tm1 = (const float*)d_in[0];
    const float* xs_h  = (const float*)d_in[1];
    const float* uh    = (const float*)d_in[2];
    const float* mask  = (const float*)d_in[3];
    const float* W_sa  = (const float*)d_in[4];
    const float* b_sa  = (const float*)d_in[5];
    const float* w_a1  = (const float*)d_in[6];
    const float* b_a1  = (const float*)d_in[7];
    float* out = (float*)d_out;  // [0 : L*B) = e_ij, [L*B : ) = attend

    k_proj<<<dim3(16, KSPLIT), 256>>>(s_tm1, W_sa);
    k_reduce<<<128, 256>>>(b_sa);
    k_scores<<<2048, 256>>>(uh, w_a1, mask, b_a1);
    k_attend<<<1024, 256>>>(xs_h, out, out + Lq * Bq);
}

// round 13
// speedup vs baseline: 1.1635x; 1.0378x over previous
#include <cuda_runtime.h>

#define Lq 128
#define Bq 128
#define Dq 1024
#define Aq 1024
#define Hq 2048
#define KSPLIT 16
#define KC (Dq / KSPLIT)   // 64 k per split block (4 k-tiles of 16)

typedef unsigned long long ull;

// Scratch (device globals: allocation-free, graph-safe)
__device__ float g_projp[KSPLIT * Bq * Aq];  // split-K partials (8MB, L2-resident)
__device__ float g_proj[Bq * Aq];            // reduced proj + bias
__device__ float g_eT[Bq * Lq];              // UNNORMALIZED e~ = exp(score+b)*mask, (B,L)

__device__ __forceinline__ float tanh_fast(float x) {
    float y;
    asm("tanh.approx.f32 %0, %1;" : "=f"(y) : "f"(x));
    return y;
}
__device__ __forceinline__ ull pack2(float x, float y) {
    ull r;
    asm("mov.b64 %0, {%1, %2};" : "=l"(r) : "f"(x), "f"(y));
    return r;
}
__device__ __forceinline__ void unpack2(ull v, float& lo, float& hi) {
    asm("mov.b64 {%0, %1}, %2;" : "=f"(lo), "=f"(hi) : "l"(v));
}
__device__ __forceinline__ ull ffma2(ull a, ull b, ull c) {
    ull d;
    asm("fma.rn.f32x2 %0, %1, %2, %3;" : "=l"(d) : "l"(a), "l"(b), "l"(c));
    return d;
}

// ---------------------------------------------------------------------------
// K1: proj partials. Register-tiled f32x2 SGEMM: 128(b) x 64(a), KT=16,
// split-K=16, grid (16,16)=256 blocks, 256 threads.
// This round: __launch_bounds__(256,1) to unlock regs (occupancy is
// grid-limited), double-buffered smem (ONE sync per k-tile), and a
// software-pipelined inner loop (smem operands for kk+1 prefetched into
// registers while kk's ffma2 chain issues) to cover the 29-cyc LDS latency.
// ---------------------------------------------------------------------------
__global__ void __launch_bounds__(256, 1) k_proj(const float* __restrict__ S,
                                                 const float* __restrict__ W) {
    const int a0    = blockIdx.x * 64;
    const int kbase = blockIdx.y * KC;

    __shared__ float As[2][16][132];  // [buf][k][m]
    __shared__ float Bs[2][16][68];   // [buf][k][n]

    const int t  = threadIdx.x;
    const int ar = t >> 1;
    const int ac = (t & 1) * 8;
    const int br = t >> 2;
    const int bc = (t & 3) * 4;
    const int tx = t & 15;
    const int ty = t >> 4;

    ull acc[4][4];
#pragma unroll
    for (int i = 0; i < 4; ++i)
#pragma unroll
        for (int j = 0; j < 4; ++j) acc[i][j] = 0ull;

    // gmem stage registers
    float4 av0, av1, bv;

    // prologue: load + store tile 0
    {
        const int k0 = kbase;
        av0 = *(const float4*)(S + (size_t)ar * Dq + k0 + ac);
        av1 = *(const float4*)(S + (size_t)ar * Dq + k0 + ac + 4);
        bv  = *(const float4*)(W + (size_t)(a0 + br) * Dq + k0 + bc);
        As[0][ac + 0][ar] = av0.x;  As[0][ac + 1][ar] = av0.y;
        As[0][ac + 2][ar] = av0.z;  As[0][ac + 3][ar] = av0.w;
        As[0][ac + 4][ar] = av1.x;  As[0][ac + 5][ar] = av1.y;
        As[0][ac + 6][ar] = av1.z;  As[0][ac + 7][ar] = av1.w;
        Bs[0][bc + 0][br] = bv.x;   Bs[0][bc + 1][br] = bv.y;
        Bs[0][bc + 2][br] = bv.z;   Bs[0][bc + 3][br] = bv.w;
    }
    __syncthreads();

#pragma unroll
    for (int kt = 0; kt < 4; ++kt) {
        const int cur = kt & 1;
        const int nxt = 1 - cur;

        // issue gmem loads for next tile (latency overlapped with compute)
        if (kt < 3) {
            const int k0 = kbase + (kt + 1) * 16;
            av0 = *(const float4*)(S + (size_t)ar * Dq + k0 + ac);
            av1 = *(const float4*)(S + (size_t)ar * Dq + k0 + ac + 4);
            bv  = *(const float4*)(W + (size_t)(a0 + br) * Dq + k0 + bc);
        }

        // compute on buffer `cur`, software-pipelined over kk
        ulonglong2 c01 = *(const ulonglong2*)&As[cur][0][ty * 8];
        ulonglong2 c23 = *(const ulonglong2*)&As[cur][0][ty * 8 + 4];
        float4     cb  = *(const float4*)&Bs[cur][0][tx * 4];
#pragma unroll
        for (int kk = 0; kk < 16; ++kk) {
            ulonglong2 n01, n23;
            float4     nb;
            if (kk < 15) {
                n01 = *(const ulonglong2*)&As[cur][kk + 1][ty * 8];
                n23 = *(const ulonglong2*)&As[cur][kk + 1][ty * 8 + 4];
                nb  = *(const float4*)&Bs[cur][kk + 1][tx * 4];
            }
            ull b0 = pack2(cb.x, cb.x), b1 = pack2(cb.y, cb.y);
            ull b2 = pack2(cb.z, cb.z), b3 = pack2(cb.w, cb.w);
            acc[0][0] = ffma2(c01.x, b0, acc[0][0]);
            acc[0][1] = ffma2(c01.x, b1, acc[0][1]);
            acc[0][2] = ffma2(c01.x, b2, acc[0][2]);
            acc[0][3] = ffma2(c01.x, b3, acc[0][3]);
            acc[1][0] = ffma2(c01.y, b0, acc[1][0]);
            acc[1][1] = ffma2(c01.y, b1, acc[1][1]);
            acc[1][2] = ffma2(c01.y, b2, acc[1][2]);
            acc[1][3] = ffma2(c01.y, b3, acc[1][3]);
            acc[2][0] = ffma2(c23.x, b0, acc[2][0]);
            acc[2][1] = ffma2(c23.x, b1, acc[2][1]);
            acc[2][2] = ffma2(c23.x, b2, acc[2][2]);
            acc[2][3] = ffma2(c23.x, b3, acc[2][3]);
            acc[3][0] = ffma2(c23.y, b0, acc[3][0]);
            acc[3][1] = ffma2(c23.y, b1, acc[3][1]);
            acc[3][2] = ffma2(c23.y, b2, acc[3][2]);
            acc[3][3] = ffma2(c23.y, b3, acc[3][3]);
            if (kk < 15) { c01 = n01;  c23 = n23;  cb = nb; }
        }

        // store next tile into the other buffer; one sync per tile.
        // (writes target buf `nxt` — no conflict with lagging readers of
        //  `cur`; the sync gates the next iteration's reads of `nxt`.)
        if (kt < 3) {
            As[nxt][ac + 0][ar] = av0.x;  As[nxt][ac + 1][ar] = av0.y;
            As[nxt][ac + 2][ar] = av0.z;  As[nxt][ac + 3][ar] = av0.w;
            As[nxt][ac + 4][ar] = av1.x;  As[nxt][ac + 5][ar] = av1.y;
            As[nxt][ac + 6][ar] = av1.z;  As[nxt][ac + 7][ar] = av1.w;
            Bs[nxt][bc + 0][br] = bv.x;   Bs[nxt][bc + 1][br] = bv.y;
            Bs[nxt][bc + 2][br] = bv.z;   Bs[nxt][bc + 3][br] = bv.w;
            __syncthreads();
        }
    }

    float* base = g_projp + (size_t)blockIdx.y * Bq * Aq + a0 + tx * 4;
#pragma unroll
    for (int mi = 0; mi < 4; ++mi) {
        float4 r0, r1;
        unpack2(acc[mi][0], r0.x, r1.x);
        unpack2(acc[mi][1], r0.y, r1.y);
        unpack2(acc[mi][2], r0.z, r1.z);
        unpack2(acc[mi][3], r0.w, r1.w);
        const int m = ty * 8 + 2 * mi;
        *(float4*)(base + (size_t)m * Aq)       = r0;
        *(float4*)(base + (size_t)(m + 1) * Aq) = r1;
    }
}

// ---------------------------------------------------------------------------
// K2: g_proj = sum_z partials + bias.
// EXACTLY covers Bq*Aq = 131072 floats = 32768 float4 = 128 blocks x 256 thr.
// ---------------------------------------------------------------------------
__global__ void __launch_bounds__(256) k_reduce(const float* __restrict__ bsa) {
    const int idx = (blockIdx.x * 256 + threadIdx.x) * 4;
    const int a   = idx & (Aq - 1);
    float4 s = *(const float4*)(bsa + a);
#pragma unroll
    for (int z = 0; z < KSPLIT; ++z) {
        float4 p = *(const float4*)(g_projp + (size_t)z * Bq * Aq + idx);
        s.x += p.x;  s.y += p.y;  s.z += p.z;  s.w += p.w;
    }
    *(float4*)(g_proj + idx) = s;
}

// ---------------------------------------------------------------------------
// K3: e~[b,l] = exp(b_a1 + sum_a w_a1[a]*tanh(proj[b,a]+uh[l,b,a])) * mask
// Warp per (l,b); 8 warps share one b. Softmax numerator fused in epilogue.
// Grid: B * L/8 = 2048 blocks, 256 threads.
// ---------------------------------------------------------------------------
__global__ void __launch_bounds__(256) k_scores(const float* __restrict__ uh,
                                                const float* __restrict__ w1,
                                                const float* __restrict__ mask,
                                                const float* __restrict__ ba1) {
    const int b  = blockIdx.x >> 4;
    const int l0 = (blockIdx.x & 15) << 3;
    __shared__ float ps[Aq];
    __shared__ float ws[Aq];
    const int t  = threadIdx.x;
    const int i4 = t * 4;

    *(float4*)&ps[i4] = *(const float4*)(g_proj + (size_t)b * Aq + i4);
    *(float4*)&ws[i4] = *(const float4*)(w1 + i4);
    __syncthreads();

    const int w    = t >> 5;
    const int lane = t & 31;
    const int l    = l0 + w;
    const float* u = uh + (size_t)(l * Bq + b) * Aq;

    float acc = 0.f;
#pragma unroll
    for (int i = 0; i < 8; ++i) {
        int idx = i * 128 + lane * 4;
        float4 u4 = __ldcs((const float4*)(u + idx));
        float4 p4 = *(const float4*)&ps[idx];
        float4 w4 = *(const float4*)&ws[idx];
        acc = fmaf(w4.x, tanh_fast(p4.x + u4.x), acc);
        acc = fmaf(w4.y, tanh_fast(p4.y + u4.y), acc);
        acc = fmaf(w4.z, tanh_fast(p4.z + u4.z), acc);
        acc = fmaf(w4.w, tanh_fast(p4.w + u4.w), acc);
    }
#pragma unroll
    for (int off = 16; off; off >>= 1)
        acc += __shfl_xor_sync(0xffffffffu, acc, off);
    if (lane == 0)
        g_eT[b * Lq + l] = __expf(acc + ba1[0]) * mask[l * Bq + b];
}

// ---------------------------------------------------------------------------
// K4: attend[b,h] = (1/S_b) * sum_l e~[l,b] * xs_h[l,b,h];  S_b = sum_l e~.
// Block = (b, 256-wide h chunk), 256 threads = 64 cols(x4) * 4 l-groups.
// h0==0 blocks also write normalized e_ij. Grid: B*8 = 1024 blocks.
// ---------------------------------------------------------------------------
__global__ void __launch_bounds__(256) k_attend(const float* __restrict__ xs,
                                                float* __restrict__ e_out,
                                                float* __restrict__ out) {
    const int b  = blockIdx.x >> 3;
    const int h0 = (blockIdx.x & 7) * 256;
    const int t  = threadIdx.x;

    __shared__ float  es[Lq];
    __shared__ float  red[4];
    __shared__ float4 pacc[256];

    float ev = 0.f;
    if (t < 128) ev = g_eT[b * Lq + t];
    float v = ev;
#pragma unroll
    for (int off = 16; off; off >>= 1)
        v += __shfl_xor_sync(0xffffffffu, v, off);
    if (t < 128) {
        if ((t & 31) == 0) red[t >> 5] = v;
        es[t] = ev;
    }
    __syncthreads();
    const float inv = 1.f / ((red[0] + red[1]) + (red[2] + red[3]));
    if (h0 == 0 && t < 128) e_out[t * Bq + b] = es[t] * inv;

    const int col = t & 63;
    const int g   = t >> 6;
    const float* base = xs + (size_t)(g * 32) * Bq * Hq +
                        (size_t)b * Hq + h0 + col * 4;
    float4 a0 = make_float4(0.f, 0.f, 0.f, 0.f);
    float4 a1 = make_float4(0.f, 0.f, 0.f, 0.f);
#pragma unroll
    for (int i = 0; i < 32; i += 2) {
        float4 v0 = __ldcs((const float4*)(base + (size_t)(i + 0) * Bq * Hq));
        float4 v1 = __ldcs((const float4*)(base + (size_t)(i + 1) * Bq * Hq));
        float e0 = es[g * 32 + i + 0];
        float e1 = es[g * 32 + i + 1];
        a0.x = fmaf(e0, v0.x, a0.x);  a0.y = fmaf(e0, v0.y, a0.y);
        a0.z = fmaf(e0, v0.z, a0.z);  a0.w = fmaf(e0, v0.w, a0.w);
        a1.x = fmaf(e1, v1.x, a1.x);  a1.y = fmaf(e1, v1.y, a1.y);
        a1.z = fmaf(e1, v1.z, a1.z);  a1.w = fmaf(e1, v1.w, a1.w);
    }
    a0.x += a1.x;  a0.y += a1.y;  a0.z += a1.z;  a0.w += a1.w;
    pacc[t] = a0;
    __syncthreads();
    if (g == 0) {
        float4 p1 = pacc[col + 64];
        float4 p2 = pacc[col + 128];
        float4 p3 = pacc[col + 192];
        a0.x = ((a0.x + p1.x) + (p2.x + p3.x)) * inv;
        a0.y = ((a0.y + p1.y) + (p2.y + p3.y)) * inv;
        a0.z = ((a0.z + p1.z) + (p2.z + p3.z)) * inv;
        a0.w = ((a0.w + p1.w) + (p2.w + p3.w)) * inv;
        *(float4*)(out + (size_t)b * Hq + h0 + col * 4) = a0;
    }
}

// ---------------------------------------------------------------------------
extern "C" void kernel_launch(void* const* d_in, const int* in_sizes, int n_in,
                              void* d_out, int out_size) {
    const float* s_tm1 = (const float*)d_in[0];
    const float* xs_h  = (const float*)d_in[1];
    const float* uh    = (const float*)d_in[2];
    const float* mask  = (const float*)d_in[3];
    const float* W_sa  = (const float*)d_in[4];
    const float* b_sa  = (const float*)d_in[5];
    const float* w_a1  = (const float*)d_in[6];
    const float* b_a1  = (const float*)d_in[7];
    float* out = (float*)d_out;  // [0 : L*B) = e_ij, [L*B : ) = attend

    k_proj<<<dim3(16, KSPLIT), 256>>>(s_tm1, W_sa);
    k_reduce<<<128, 256>>>(b_sa);
    k_scores<<<2048, 256>>>(uh, w_a1, mask, b_a1);
    k_attend<<<1024, 256>>>(xs_h, out, out + Lq * Bq);
}